// round 6
// baseline (speedup 1.0000x reference)
#include <cuda_runtime.h>
#include <cuda_bf16.h>
#include <stdint.h>
#include <math.h>

// ---------------------------------------------------------------------------
// Problem constants
// ---------------------------------------------------------------------------
#define MTOK 16384        // B*N tokens
#define DDIM 1024         // hidden dim
#define NEXP 8            // experts
#define FDIM 512          // expert dim
#define KEF  4096         // NEXP*FDIM

// GEMM tiling: block 128x128, warp tile 64x32 (8 warps: 2m x 4n), BK=32
#define BM 128
#define BN 128
#define BK 32
#define NSTAGE 3
#define OFF_AHI 0
#define OFF_ALO 8192
#define OFF_BHI 16384
#define OFF_BLO 24576
#define STAGE_BYTES 32768
#define SMEM_MAIN (NSTAGE * STAGE_BYTES)      // 96 KB
#define SMEM_TOTAL (SMEM_MAIN + 4096)         // + b2 bias tile (8x128 fp32)

// Persistent scheduler
#define NBM        (MTOK / BM)                    // 128 m-blocks
#define FC1_PER_BM ((FDIM / BN) * NEXP)           // 32
#define FC2_PER_BM (DDIM / BN)                    // 8
#define LAG        8
#define N_HEAD     (LAG * FC1_PER_BM)             // 256
#define N_GROUPS   (NBM - LAG)                    // 120
#define GROUP_SZ   (FC1_PER_BM + FC2_PER_BM)      // 40
#define N_MID      (N_GROUPS * GROUP_SZ)          // 4800
#define NTILES     (NBM * GROUP_SZ)               // 5120
#define PERSIST_CTAS 296                          // 2 per SM on 148 SMs

// ---------------------------------------------------------------------------
// Global scratch (static __device__ — no allocation)
// ---------------------------------------------------------------------------
static __device__ __align__(256) float         g_router[MTOK * NEXP];
static __device__ __align__(256) __nv_bfloat16 g_xhi[(size_t)MTOK * DDIM];
static __device__ __align__(256) __nv_bfloat16 g_xlo[(size_t)MTOK * DDIM];
static __device__ __align__(256) __nv_bfloat16 g_w1t_hi[(size_t)NEXP * FDIM * DDIM]; // [e][f][d]
static __device__ __align__(256) __nv_bfloat16 g_w1t_lo[(size_t)NEXP * FDIM * DDIM];
static __device__ __align__(256) __nv_bfloat16 g_w2t_hi[(size_t)DDIM * KEF];         // [d][ef]
static __device__ __align__(256) __nv_bfloat16 g_w2t_lo[(size_t)DDIM * KEF];
static __device__ __align__(256) __nv_bfloat16 g_ghi[(size_t)MTOK * KEF];
static __device__ __align__(256) __nv_bfloat16 g_glo[(size_t)MTOK * KEF];
static __device__ int g_tile_ctr;
static __device__ int g_fc1_cnt[NBM];

// ---------------------------------------------------------------------------
// Helpers (base ISA only)
// ---------------------------------------------------------------------------
__device__ __forceinline__ uint32_t ea_smem_u32(const void* p) {
    uint32_t a;
    asm("{ .reg .u64 t; cvta.to.shared.u64 t, %1; cvt.u32.u64 %0, t; }" : "=r"(a) : "l"(p));
    return a;
}
// Logical (row r, 16B-chunk c in 0..3) -> conflict-free physical byte offset.
__device__ __forceinline__ uint32_t ea_sw(int r, int c) {
    return ((uint32_t)(r >> 1) << 7) |
           ((uint32_t)(((((r & 1) << 2) | c) ^ ((r >> 1) & 7))) << 4);
}
__device__ __forceinline__ void ea_cp16(uint32_t s, const void* g) {
    asm volatile("cp.async.cg.shared.global [%0], [%1], 16;\n" :: "r"(s), "l"(g));
}
__device__ __forceinline__ void ea_cp_commit() { asm volatile("cp.async.commit_group;\n"); }
template <int N>
__device__ __forceinline__ void ea_cp_wait() { asm volatile("cp.async.wait_group %0;\n" :: "n"(N)); }

__device__ __forceinline__ void ea_ldsm4(uint32_t* r, uint32_t a) {
    asm volatile("ldmatrix.sync.aligned.m8n8.x4.shared.b16 {%0,%1,%2,%3}, [%4];\n"
                 : "=r"(r[0]), "=r"(r[1]), "=r"(r[2]), "=r"(r[3]) : "r"(a));
}
__device__ __forceinline__ void ea_mma(float* d, const uint32_t* a, uint32_t b0, uint32_t b1) {
    asm volatile(
        "mma.sync.aligned.m16n8k16.row.col.f32.bf16.bf16.f32 "
        "{%0,%1,%2,%3}, {%4,%5,%6,%7}, {%8,%9}, {%0,%1,%2,%3};\n"
        : "+f"(d[0]), "+f"(d[1]), "+f"(d[2]), "+f"(d[3])
        : "r"(a[0]), "r"(a[1]), "r"(a[2]), "r"(a[3]), "r"(b0), "r"(b1));
}
__device__ __forceinline__ uint32_t ea_pack2(__nv_bfloat16 a, __nv_bfloat16 b) {
    return (uint32_t)__bfloat16_as_ushort(a) | ((uint32_t)__bfloat16_as_ushort(b) << 16);
}
__device__ __forceinline__ void ea_split(float v, __nv_bfloat16& h, __nv_bfloat16& l) {
    h = __float2bfloat16(v);
    l = __float2bfloat16(v - __bfloat162float(h));
}
__device__ __forceinline__ float ea_gelu(float v) {
    return 0.5f * v * (1.0f + erff(v * 0.70710678118654752f));
}

// ---------------------------------------------------------------------------
// Scheduler state init (fresh every launch — graph-replay safe)
// ---------------------------------------------------------------------------
__global__ void init_sched_kernel()
{
    if (threadIdx.x == 0) g_tile_ctr = 0;
    if (threadIdx.x < NBM) g_fc1_cnt[threadIdx.x] = 0;
}

// ---------------------------------------------------------------------------
// Fused router + x hi/lo split. One block per token, 256 thr = 4 floats each.
// ---------------------------------------------------------------------------
__global__ void __launch_bounds__(256) router_convert_kernel(
    const float* __restrict__ x, const float* __restrict__ Wr, const float* __restrict__ br)
{
    const int t = blockIdx.x;
    const int tid = threadIdx.x;
    const int warp = tid >> 5, lane = tid & 31;
    __shared__ float part[8][NEXP];

    const size_t base4 = (size_t)t * (DDIM / 4) + tid;   // float4 index
    float4 v = ((const float4*)x)[base4];

    __nv_bfloat16 h0, h1, h2, h3, l0, l1, l2, l3;
    ea_split(v.x, h0, l0); ea_split(v.y, h1, l1);
    ea_split(v.z, h2, l2); ea_split(v.w, h3, l3);
    ((uint2*)g_xhi)[base4] = make_uint2(ea_pack2(h0, h1), ea_pack2(h2, h3));
    ((uint2*)g_xlo)[base4] = make_uint2(ea_pack2(l0, l1), ea_pack2(l2, l3));

    const float* wr = Wr + (size_t)tid * 4 * NEXP;
    float acc[NEXP];
    #pragma unroll
    for (int e = 0; e < NEXP; e++)
        acc[e] = v.x * wr[e] + v.y * wr[NEXP + e] + v.z * wr[2 * NEXP + e] + v.w * wr[3 * NEXP + e];
    #pragma unroll
    for (int o = 16; o > 0; o >>= 1)
        #pragma unroll
        for (int e = 0; e < NEXP; e++)
            acc[e] += __shfl_xor_sync(0xffffffffu, acc[e], o);
    if (lane == 0)
        #pragma unroll
        for (int e = 0; e < NEXP; e++) part[warp][e] = acc[e];
    __syncthreads();

    if (warp == 0 && lane < NEXP) {
        float s = br[lane];
        #pragma unroll
        for (int w = 0; w < 8; w++) s += part[w][lane];
        float mx = s;
        #pragma unroll
        for (int o = 4; o > 0; o >>= 1) mx = fmaxf(mx, __shfl_xor_sync(0xffu, mx, o, 8));
        float ex = expf(s - mx);
        float tot = ex;
        #pragma unroll
        for (int o = 4; o > 0; o >>= 1) tot += __shfl_xor_sync(0xffu, tot, o, 8);
        g_router[t * NEXP + lane] = ex / tot;
    }
}

// ---------------------------------------------------------------------------
// Transposing split: src[rows][cols] fp32 -> dst[cols][rows] bf16 hi/lo
// ---------------------------------------------------------------------------
template <int WHICH>
__global__ void __launch_bounds__(256) transpose_split_kernel(
    const float* __restrict__ src, int rows, int cols)
{
    __shared__ float tile[32][33];
    const size_t zoff = (size_t)blockIdx.z * rows * cols;
    const float* s = src + zoff;
    __nv_bfloat16* dhi = (WHICH == 0 ? g_w1t_hi : g_w2t_hi) + zoff;
    __nv_bfloat16* dlo = (WHICH == 0 ? g_w1t_lo : g_w2t_lo) + zoff;

    int x = blockIdx.x * 32 + threadIdx.x;
    int y0 = blockIdx.y * 32;
    #pragma unroll
    for (int j = 0; j < 32; j += 8)
        tile[threadIdx.y + j][threadIdx.x] = s[(size_t)(y0 + threadIdx.y + j) * cols + x];
    __syncthreads();
    int xo = blockIdx.y * 32 + threadIdx.x;
    int yo = blockIdx.x * 32;
    #pragma unroll
    for (int j = 0; j < 32; j += 8) {
        float v = tile[threadIdx.x][threadIdx.y + j];
        __nv_bfloat16 h, l; ea_split(v, h, l);
        size_t o = (size_t)(yo + threadIdx.y + j) * rows + xo;
        dhi[o] = h; dlo[o] = l;
    }
}

// ---------------------------------------------------------------------------
// Persistent fused MoE GEMM kernel: atomic tile scheduler runs FC1 and FC2
// tiles interleaved (FC2 lags FC1 by LAG m-blocks; dependency via counters).
// Same bf16x3 mma.sync mainloop as round 5.
// ---------------------------------------------------------------------------
__global__ void __launch_bounds__(256, 2) moe_persistent_kernel(
    const float* __restrict__ b1, const float* __restrict__ b2, float* __restrict__ out)
{
    extern __shared__ char smem[];
    const uint32_t sb = ea_smem_u32(smem);
    __shared__ int s_tile;
    const int tid = threadIdx.x;
    const int wid = tid >> 5, lane = tid & 31;
    const int wm = wid & 1, wn = wid >> 1;    // 2 x 4 warp grid, 64x32 tiles
    const int lrow = lane >> 2;               // 0..7
    const int lcol = (lane & 3) << 1;         // 0,2,4,6

    for (;;) {
        if (tid == 0) s_tile = atomicAdd(&g_tile_ctr, 1);
        __syncthreads();
        const int id = s_tile;
        if (id >= NTILES) break;

        // ---- decode tile id -> (kind, bm, sub) ----
        int kind, bm, sub;
        if (id < N_HEAD) {
            kind = 0; bm = id / FC1_PER_BM; sub = id % FC1_PER_BM;
        } else if (id < N_HEAD + N_MID) {
            int t = id - N_HEAD, g = t / GROUP_SZ, r = t % GROUP_SZ;
            if (r < FC1_PER_BM) { kind = 0; bm = LAG + g; sub = r; }
            else                { kind = 1; bm = g;       sub = r - FC1_PER_BM; }
        } else {
            int t = id - (N_HEAD + N_MID);
            kind = 1; bm = (NBM - LAG) + t / FC2_PER_BM; sub = t % FC2_PER_BM;
        }
        const int bm0 = bm * BM;

        int e = 0, bn0, nk, lda, ldb;
        const __nv_bfloat16 *Ahi, *Alo, *Bhi, *Blo;
        if (kind == 0) {
            e = sub >> 2; bn0 = (sub & 3) * BN;
            Ahi = g_xhi; Alo = g_xlo; lda = DDIM;
            const size_t wo = (size_t)e * FDIM * DDIM;
            Bhi = g_w1t_hi + wo; Blo = g_w1t_lo + wo; ldb = DDIM;
            nk = DDIM / BK;
        } else {
            bn0 = sub * BN;
            Ahi = g_ghi; Alo = g_glo; lda = KEF;
            Bhi = g_w2t_hi; Blo = g_w2t_lo; ldb = KEF;
            nk = KEF / BK;
            if (tid == 0) {   // dependency: all 32 FC1 tiles of this m-block done
                while (atomicAdd(&g_fc1_cnt[bm], 0) < FC1_PER_BM) __nanosleep(64);
            }
        }
        __syncthreads();

        if (kind == 1) {   // stage b2 tile [8][BN]
            float* b2s = (float*)(smem + SMEM_MAIN);
            #pragma unroll
            for (int it = 0; it < 4; it++) {
                int idx = tid + it * 256;
                b2s[idx] = b2[(idx >> 7) * DDIM + bn0 + (idx & 127)];
            }
        }

        float acc[4][4][4];
        #pragma unroll
        for (int a = 0; a < 4; a++)
            #pragma unroll
            for (int b = 0; b < 4; b++)
                #pragma unroll
                for (int c = 0; c < 4; c++) acc[a][b][c] = 0.0f;

        auto load_stage = [&](int stg, int kk) {
            const uint32_t base = sb + stg * STAGE_BYTES;
            #pragma unroll
            for (int it = 0; it < 2; it++) {
                int idx = tid + it * 256;
                int r = idx >> 2, c = idx & 3;
                uint32_t so = ea_sw(r, c);
                size_t ga = (size_t)(bm0 + r) * lda + kk + c * 8;
                size_t gb = (size_t)(bn0 + r) * ldb + kk + c * 8;
                ea_cp16(base + OFF_AHI + so, Ahi + ga);
                ea_cp16(base + OFF_ALO + so, Alo + ga);
                ea_cp16(base + OFF_BHI + so, Bhi + gb);
                ea_cp16(base + OFF_BLO + so, Blo + gb);
            }
        };

        auto compute_stage = [&](int stg) {
            const uint32_t base = sb + stg * STAGE_BYTES;
            #pragma unroll
            for (int s = 0; s < 2; s++) {             // two k16 steps per BK
                uint32_t ah[4][4], al[4][4], bh[2][4], bl[2][4];
                const int arow = wm * 64 + (lane & 7) + ((lane >> 3) & 1) * 8;
                const int acol = s * 2 + ((lane >> 4) & 1);
                #pragma unroll
                for (int mi = 0; mi < 4; mi++) {
                    uint32_t off = ea_sw(arow + mi * 16, acol);
                    ea_ldsm4(ah[mi], base + OFF_AHI + off);
                    ea_ldsm4(al[mi], base + OFF_ALO + off);
                }
                const int brow = wn * 32 + (lane & 7) + ((lane >> 4) & 1) * 8;
                const int bcol = s * 2 + ((lane >> 3) & 1);
                #pragma unroll
                for (int bi = 0; bi < 2; bi++) {
                    uint32_t off = ea_sw(brow + bi * 16, bcol);
                    ea_ldsm4(bh[bi], base + OFF_BHI + off);
                    ea_ldsm4(bl[bi], base + OFF_BLO + off);
                }
                // pass-major order: 16 independent mma per pass (no RAW runs)
                #pragma unroll
                for (int mi = 0; mi < 4; mi++)
                    #pragma unroll
                    for (int ni = 0; ni < 4; ni++)
                        ea_mma(acc[mi][ni], ah[mi], bh[ni >> 1][(ni & 1) * 2], bh[ni >> 1][(ni & 1) * 2 + 1]);
                #pragma unroll
                for (int mi = 0; mi < 4; mi++)
                    #pragma unroll
                    for (int ni = 0; ni < 4; ni++)
                        ea_mma(acc[mi][ni], ah[mi], bl[ni >> 1][(ni & 1) * 2], bl[ni >> 1][(ni & 1) * 2 + 1]);
                #pragma unroll
                for (int mi = 0; mi < 4; mi++)
                    #pragma unroll
                    for (int ni = 0; ni < 4; ni++)
                        ea_mma(acc[mi][ni], al[mi], bh[ni >> 1][(ni & 1) * 2], bh[ni >> 1][(ni & 1) * 2 + 1]);
            }
        };

        // 3-stage pipeline, one __syncthreads per iteration.
        load_stage(0, 0);   ea_cp_commit();
        load_stage(1, BK);  ea_cp_commit();

        #pragma unroll 1
        for (int ck = 0; ck < nk; ck++) {
            ea_cp_wait<1>();
            __syncthreads();
            if (ck + NSTAGE - 1 < nk) load_stage((ck + NSTAGE - 1) % 3, (ck + NSTAGE - 1) * BK);
            ea_cp_commit();
            compute_stage(ck % 3);
        }

        // ------------------------------ epilogue ----------------------------
        if (kind == 0) {
            #pragma unroll
            for (int mi = 0; mi < 4; mi++) {
                #pragma unroll
                for (int p = 0; p < 2; p++) {
                    const int m = bm0 + wm * 64 + mi * 16 + lrow + p * 8;
                    const float wr = g_router[m * NEXP + e];
                    const size_t rowo = (size_t)m * KEF + e * FDIM + bn0 + wn * 32;
                    #pragma unroll
                    for (int ni = 0; ni < 4; ni++) {
                        const int n = bn0 + wn * 32 + ni * 8 + lcol;
                        float v0 = acc[mi][ni][p * 2 + 0] + b1[e * FDIM + n];
                        float v1 = acc[mi][ni][p * 2 + 1] + b1[e * FDIM + n + 1];
                        v0 = ea_gelu(v0) * wr;
                        v1 = ea_gelu(v1) * wr;
                        __nv_bfloat16 h0, l0, h1, l1;
                        ea_split(v0, h0, l0); ea_split(v1, h1, l1);
                        *(uint32_t*)(g_ghi + rowo + ni * 8 + lcol) = ea_pack2(h0, h1);
                        *(uint32_t*)(g_glo + rowo + ni * 8 + lcol) = ea_pack2(l0, l1);
                    }
                }
            }
            __threadfence();              // make G visible before signaling
        } else {
            const float* b2s = (const float*)(smem + SMEM_MAIN);
            #pragma unroll
            for (int mi = 0; mi < 4; mi++) {
                #pragma unroll
                for (int p = 0; p < 2; p++) {
                    const int m = bm0 + wm * 64 + mi * 16 + lrow + p * 8;
                    float4 w0 = *(const float4*)(g_router + (size_t)m * NEXP);
                    float4 w1 = *(const float4*)(g_router + (size_t)m * NEXP + 4);
                    float wr[NEXP] = {w0.x, w0.y, w0.z, w0.w, w1.x, w1.y, w1.z, w1.w};
                    float* orow = out + (size_t)m * DDIM + bn0;
                    #pragma unroll
                    for (int ni = 0; ni < 4; ni++) {
                        const int nl = wn * 32 + ni * 8 + lcol;
                        float bias0 = 0.0f, bias1 = 0.0f;
                        #pragma unroll
                        for (int ee = 0; ee < NEXP; ee++) {
                            bias0 = fmaf(wr[ee], b2s[ee * BN + nl], bias0);
                            bias1 = fmaf(wr[ee], b2s[ee * BN + nl + 1], bias1);
                        }
                        float2 res = make_float2(acc[mi][ni][p * 2 + 0] + bias0,
                                                 acc[mi][ni][p * 2 + 1] + bias1);
                        *(float2*)(orow + nl) = res;
                    }
                }
            }
        }

        __syncthreads();                  // all stores done; safe to signal & reclaim
        if (kind == 0 && tid == 0) atomicAdd(&g_fc1_cnt[bm], 1);
    }
}

// ---------------------------------------------------------------------------
extern "C" void kernel_launch(void* const* d_in, const int* in_sizes, int n_in,
                              void* d_out, int out_size)
{
    const float* x  = (const float*)d_in[0];
    const float* W1 = (const float*)d_in[1];
    const float* b1 = (const float*)d_in[2];
    const float* W2 = (const float*)d_in[3];
    const float* b2 = (const float*)d_in[4];
    const float* Wr = (const float*)d_in[5];
    const float* br = (const float*)d_in[6];
    float* out = (float*)d_out;

    cudaFuncSetAttribute(moe_persistent_kernel, cudaFuncAttributeMaxDynamicSharedMemorySize, SMEM_TOTAL);

    init_sched_kernel<<<1, 128>>>();
    router_convert_kernel<<<MTOK, 256>>>(x, Wr, br);
    transpose_split_kernel<0><<<dim3(FDIM / 32, DDIM / 32, NEXP), dim3(32, 8)>>>(W1, DDIM, FDIM);
    transpose_split_kernel<1><<<dim3(DDIM / 32, KEF / 32, 1), dim3(32, 8)>>>(W2, KEF, DDIM);

    moe_persistent_kernel<<<PERSIST_CTAS, 256, SMEM_TOTAL>>>(b1, b2, out);
}

// round 7
// speedup vs baseline: 1.0722x; 1.0722x over previous
#include <cuda_runtime.h>
#include <cuda_bf16.h>
#include <stdint.h>
#include <math.h>

// ---------------------------------------------------------------------------
// Problem constants
// ---------------------------------------------------------------------------
#define MTOK 16384        // B*N tokens
#define DDIM 1024         // hidden dim
#define NEXP 8            // experts
#define FDIM 512          // expert dim
#define KEF  4096         // NEXP*FDIM

// GEMM tiling: block 128x128, warp tile 64x32 (8 warps: 2m x 4n), BK=32
#define BM 128
#define BN 128
#define BK 32
#define NSTAGE 3
#define OFF_AHI 0
#define OFF_ALO 8192
#define OFF_BHI 16384
#define OFF_BLO 24576
#define STAGE_BYTES 32768
#define SMEM_MAIN (NSTAGE * STAGE_BYTES)      // 96 KB
#define SMEM_TOTAL (SMEM_MAIN + 4096)         // + b2 bias tile (8x128 fp32)

// Persistent scheduling
#define PERSIST_CTAS 296                      // 2 per SM on 148 SMs
#define NTILES_FC1 ((MTOK / BM) * (FDIM / BN) * NEXP)   // 4096
#define NTILES_FC2 ((MTOK / BM) * (DDIM / BN))          // 1024

// ---------------------------------------------------------------------------
// Global scratch (static __device__ — no allocation)
// ---------------------------------------------------------------------------
static __device__ __align__(256) float         g_router[MTOK * NEXP];
static __device__ __align__(256) __nv_bfloat16 g_xhi[(size_t)MTOK * DDIM];
static __device__ __align__(256) __nv_bfloat16 g_xlo[(size_t)MTOK * DDIM];
static __device__ __align__(256) __nv_bfloat16 g_w1t_hi[(size_t)NEXP * FDIM * DDIM]; // [e][f][d]
static __device__ __align__(256) __nv_bfloat16 g_w1t_lo[(size_t)NEXP * FDIM * DDIM];
static __device__ __align__(256) __nv_bfloat16 g_w2t_hi[(size_t)DDIM * KEF];         // [d][ef]
static __device__ __align__(256) __nv_bfloat16 g_w2t_lo[(size_t)DDIM * KEF];
static __device__ __align__(256) __nv_bfloat16 g_ghi[(size_t)MTOK * KEF];
static __device__ __align__(256) __nv_bfloat16 g_glo[(size_t)MTOK * KEF];
static __device__ int g_ctr_fc1;
static __device__ int g_ctr_fc2;

// ---------------------------------------------------------------------------
// Helpers (base ISA only)
// ---------------------------------------------------------------------------
__device__ __forceinline__ uint32_t ea_smem_u32(const void* p) {
    uint32_t a;
    asm("{ .reg .u64 t; cvta.to.shared.u64 t, %1; cvt.u32.u64 %0, t; }" : "=r"(a) : "l"(p));
    return a;
}
// Logical (row r, 16B-chunk c in 0..3) -> conflict-free physical byte offset.
__device__ __forceinline__ uint32_t ea_sw(int r, int c) {
    return ((uint32_t)(r >> 1) << 7) |
           ((uint32_t)(((((r & 1) << 2) | c) ^ ((r >> 1) & 7))) << 4);
}
__device__ __forceinline__ void ea_cp16(uint32_t s, const void* g) {
    asm volatile("cp.async.cg.shared.global [%0], [%1], 16;\n" :: "r"(s), "l"(g));
}
__device__ __forceinline__ void ea_cp_commit() { asm volatile("cp.async.commit_group;\n"); }
template <int N>
__device__ __forceinline__ void ea_cp_wait() { asm volatile("cp.async.wait_group %0;\n" :: "n"(N)); }

__device__ __forceinline__ void ea_ldsm4(uint32_t* r, uint32_t a) {
    asm volatile("ldmatrix.sync.aligned.m8n8.x4.shared.b16 {%0,%1,%2,%3}, [%4];\n"
                 : "=r"(r[0]), "=r"(r[1]), "=r"(r[2]), "=r"(r[3]) : "r"(a));
}
__device__ __forceinline__ void ea_mma(float* d, const uint32_t* a, uint32_t b0, uint32_t b1) {
    asm volatile(
        "mma.sync.aligned.m16n8k16.row.col.f32.bf16.bf16.f32 "
        "{%0,%1,%2,%3}, {%4,%5,%6,%7}, {%8,%9}, {%0,%1,%2,%3};\n"
        : "+f"(d[0]), "+f"(d[1]), "+f"(d[2]), "+f"(d[3])
        : "r"(a[0]), "r"(a[1]), "r"(a[2]), "r"(a[3]), "r"(b0), "r"(b1));
}
__device__ __forceinline__ uint32_t ea_pack2(__nv_bfloat16 a, __nv_bfloat16 b) {
    return (uint32_t)__bfloat16_as_ushort(a) | ((uint32_t)__bfloat16_as_ushort(b) << 16);
}
__device__ __forceinline__ void ea_split(float v, __nv_bfloat16& h, __nv_bfloat16& l) {
    h = __float2bfloat16(v);
    l = __float2bfloat16(v - __bfloat162float(h));
}
__device__ __forceinline__ float ea_gelu(float v) {
    return 0.5f * v * (1.0f + erff(v * 0.70710678118654752f));
}

// ---------------------------------------------------------------------------
// Scheduler counters init (fresh every launch — graph-replay safe)
// ---------------------------------------------------------------------------
__global__ void init_sched_kernel()
{
    if (threadIdx.x == 0) { g_ctr_fc1 = 0; g_ctr_fc2 = 0; }
}

// ---------------------------------------------------------------------------
// Fused router + x hi/lo split. One block per token, 256 thr = 4 floats each.
// ---------------------------------------------------------------------------
__global__ void __launch_bounds__(256) router_convert_kernel(
    const float* __restrict__ x, const float* __restrict__ Wr, const float* __restrict__ br)
{
    const int t = blockIdx.x;
    const int tid = threadIdx.x;
    const int warp = tid >> 5, lane = tid & 31;
    __shared__ float part[8][NEXP];

    const size_t base4 = (size_t)t * (DDIM / 4) + tid;   // float4 index
    float4 v = ((const float4*)x)[base4];

    __nv_bfloat16 h0, h1, h2, h3, l0, l1, l2, l3;
    ea_split(v.x, h0, l0); ea_split(v.y, h1, l1);
    ea_split(v.z, h2, l2); ea_split(v.w, h3, l3);
    ((uint2*)g_xhi)[base4] = make_uint2(ea_pack2(h0, h1), ea_pack2(h2, h3));
    ((uint2*)g_xlo)[base4] = make_uint2(ea_pack2(l0, l1), ea_pack2(l2, l3));

    const float* wr = Wr + (size_t)tid * 4 * NEXP;
    float acc[NEXP];
    #pragma unroll
    for (int e = 0; e < NEXP; e++)
        acc[e] = v.x * wr[e] + v.y * wr[NEXP + e] + v.z * wr[2 * NEXP + e] + v.w * wr[3 * NEXP + e];
    #pragma unroll
    for (int o = 16; o > 0; o >>= 1)
        #pragma unroll
        for (int e = 0; e < NEXP; e++)
            acc[e] += __shfl_xor_sync(0xffffffffu, acc[e], o);
    if (lane == 0)
        #pragma unroll
        for (int e = 0; e < NEXP; e++) part[warp][e] = acc[e];
    __syncthreads();

    if (warp == 0 && lane < NEXP) {
        float s = br[lane];
        #pragma unroll
        for (int w = 0; w < 8; w++) s += part[w][lane];
        float mx = s;
        #pragma unroll
        for (int o = 4; o > 0; o >>= 1) mx = fmaxf(mx, __shfl_xor_sync(0xffu, mx, o, 8));
        float ex = expf(s - mx);
        float tot = ex;
        #pragma unroll
        for (int o = 4; o > 0; o >>= 1) tot += __shfl_xor_sync(0xffu, tot, o, 8);
        g_router[t * NEXP + lane] = ex / tot;
    }
}

// ---------------------------------------------------------------------------
// Transposing split: src[rows][cols] fp32 -> dst[cols][rows] bf16 hi/lo
// ---------------------------------------------------------------------------
template <int WHICH>
__global__ void __launch_bounds__(256) transpose_split_kernel(
    const float* __restrict__ src, int rows, int cols)
{
    __shared__ float tile[32][33];
    const size_t zoff = (size_t)blockIdx.z * rows * cols;
    const float* s = src + zoff;
    __nv_bfloat16* dhi = (WHICH == 0 ? g_w1t_hi : g_w2t_hi) + zoff;
    __nv_bfloat16* dlo = (WHICH == 0 ? g_w1t_lo : g_w2t_lo) + zoff;

    int x = blockIdx.x * 32 + threadIdx.x;
    int y0 = blockIdx.y * 32;
    #pragma unroll
    for (int j = 0; j < 32; j += 8)
        tile[threadIdx.y + j][threadIdx.x] = s[(size_t)(y0 + threadIdx.y + j) * cols + x];
    __syncthreads();
    int xo = blockIdx.y * 32 + threadIdx.x;
    int yo = blockIdx.x * 32;
    #pragma unroll
    for (int j = 0; j < 32; j += 8) {
        float v = tile[threadIdx.x][threadIdx.y + j];
        __nv_bfloat16 h, l; ea_split(v, h, l);
        size_t o = (size_t)(yo + threadIdx.y + j) * rows + xo;
        dhi[o] = h; dlo[o] = l;
    }
}

// ---------------------------------------------------------------------------
// Persistent GEMM via mma.sync bf16x3. MODE 0 = FC1, MODE 1 = FC2.
// Work-stealing atomic tile counter kills wave-quantization tails.
// Tiles within one kernel are independent — no dependency spins.
// ---------------------------------------------------------------------------
template <int MODE>
__global__ void __launch_bounds__(256, 2) gemm_persistent_kernel(
    const float* __restrict__ bias,   // b1 [E,F] or b2 [E,D]
    float* __restrict__ out)          // MODE 1 only
{
    extern __shared__ char smem[];
    const uint32_t sb = ea_smem_u32(smem);
    __shared__ int s_tile;
    const int tid = threadIdx.x;
    const int wid = tid >> 5, lane = tid & 31;
    const int wm = wid & 1, wn = wid >> 1;    // 2 x 4 warp grid, 64x32 tiles
    const int lrow = lane >> 2;               // 0..7
    const int lcol = (lane & 3) << 1;         // 0,2,4,6
    const int ntiles = (MODE == 0) ? NTILES_FC1 : NTILES_FC2;

    for (;;) {
        if (tid == 0) s_tile = atomicAdd(MODE == 0 ? &g_ctr_fc1 : &g_ctr_fc2, 1);
        __syncthreads();
        const int id = s_tile;
        if (id >= ntiles) break;

        // decode: n/e-fastest (same concurrency footprint as round-5 raster)
        int e = 0, bm0, bn0, nk, lda, ldb;
        const __nv_bfloat16 *Ahi, *Alo, *Bhi, *Blo;
        if (MODE == 0) {
            const int sub = id & 31;            // 32 FC1 tiles per m-block
            bm0 = (id >> 5) * BM;
            e = sub >> 2; bn0 = (sub & 3) * BN;
            Ahi = g_xhi; Alo = g_xlo; lda = DDIM;
            const size_t wo = (size_t)e * FDIM * DDIM;
            Bhi = g_w1t_hi + wo; Blo = g_w1t_lo + wo; ldb = DDIM;
            nk = DDIM / BK;
        } else {
            bm0 = (id >> 3) * BM;
            bn0 = (id & 7) * BN;
            Ahi = g_ghi; Alo = g_glo; lda = KEF;
            Bhi = g_w2t_hi; Blo = g_w2t_lo; ldb = KEF;
            nk = KEF / BK;
        }

        if (MODE == 1) {   // stage b2 tile [8][BN]
            float* b2s = (float*)(smem + SMEM_MAIN);
            #pragma unroll
            for (int it = 0; it < 4; it++) {
                int idx = tid + it * 256;
                b2s[idx] = bias[(idx >> 7) * DDIM + bn0 + (idx & 127)];
            }
        }

        float acc[4][4][4];
        #pragma unroll
        for (int a = 0; a < 4; a++)
            #pragma unroll
            for (int b = 0; b < 4; b++)
                #pragma unroll
                for (int c = 0; c < 4; c++) acc[a][b][c] = 0.0f;

        auto load_stage = [&](int stg, int kk) {
            const uint32_t base = sb + stg * STAGE_BYTES;
            #pragma unroll
            for (int it = 0; it < 2; it++) {
                int idx = tid + it * 256;
                int r = idx >> 2, c = idx & 3;
                uint32_t so = ea_sw(r, c);
                size_t ga = (size_t)(bm0 + r) * lda + kk + c * 8;
                size_t gb = (size_t)(bn0 + r) * ldb + kk + c * 8;
                ea_cp16(base + OFF_AHI + so, Ahi + ga);
                ea_cp16(base + OFF_ALO + so, Alo + ga);
                ea_cp16(base + OFF_BHI + so, Bhi + gb);
                ea_cp16(base + OFF_BLO + so, Blo + gb);
            }
        };

        auto compute_stage = [&](int stg) {
            const uint32_t base = sb + stg * STAGE_BYTES;
            #pragma unroll
            for (int s = 0; s < 2; s++) {             // two k16 steps per BK
                uint32_t ah[4][4], al[4][4], bh[2][4], bl[2][4];
                const int arow = wm * 64 + (lane & 7) + ((lane >> 3) & 1) * 8;
                const int acol = s * 2 + ((lane >> 4) & 1);
                #pragma unroll
                for (int mi = 0; mi < 4; mi++) {
                    uint32_t off = ea_sw(arow + mi * 16, acol);
                    ea_ldsm4(ah[mi], base + OFF_AHI + off);
                    ea_ldsm4(al[mi], base + OFF_ALO + off);
                }
                const int brow = wn * 32 + (lane & 7) + ((lane >> 4) & 1) * 8;
                const int bcol = s * 2 + ((lane >> 3) & 1);
                #pragma unroll
                for (int bi = 0; bi < 2; bi++) {
                    uint32_t off = ea_sw(brow + bi * 16, bcol);
                    ea_ldsm4(bh[bi], base + OFF_BHI + off);
                    ea_ldsm4(bl[bi], base + OFF_BLO + off);
                }
                // pass-major: 16 independent mma per pass (no RAW chains)
                #pragma unroll
                for (int mi = 0; mi < 4; mi++)
                    #pragma unroll
                    for (int ni = 0; ni < 4; ni++)
                        ea_mma(acc[mi][ni], ah[mi], bh[ni >> 1][(ni & 1) * 2], bh[ni >> 1][(ni & 1) * 2 + 1]);
                #pragma unroll
                for (int mi = 0; mi < 4; mi++)
                    #pragma unroll
                    for (int ni = 0; ni < 4; ni++)
                        ea_mma(acc[mi][ni], ah[mi], bl[ni >> 1][(ni & 1) * 2], bl[ni >> 1][(ni & 1) * 2 + 1]);
                #pragma unroll
                for (int mi = 0; mi < 4; mi++)
                    #pragma unroll
                    for (int ni = 0; ni < 4; ni++)
                        ea_mma(acc[mi][ni], al[mi], bh[ni >> 1][(ni & 1) * 2], bh[ni >> 1][(ni & 1) * 2 + 1]);
            }
        };

        // 3-stage pipeline, one __syncthreads per iteration.
        load_stage(0, 0);   ea_cp_commit();
        load_stage(1, BK);  ea_cp_commit();

        #pragma unroll 1
        for (int ck = 0; ck < nk; ck++) {
            ea_cp_wait<1>();
            __syncthreads();
            if (ck + NSTAGE - 1 < nk) load_stage((ck + NSTAGE - 1) % 3, (ck + NSTAGE - 1) * BK);
            ea_cp_commit();
            compute_stage(ck % 3);
        }

        // ------------------------------ epilogue ----------------------------
        if (MODE == 0) {
            #pragma unroll
            for (int mi = 0; mi < 4; mi++) {
                #pragma unroll
                for (int p = 0; p < 2; p++) {
                    const int m = bm0 + wm * 64 + mi * 16 + lrow + p * 8;
                    const float wr = g_router[m * NEXP + e];
                    const size_t rowo = (size_t)m * KEF + e * FDIM + bn0 + wn * 32;
                    #pragma unroll
                    for (int ni = 0; ni < 4; ni++) {
                        const int n = bn0 + wn * 32 + ni * 8 + lcol;
                        float v0 = acc[mi][ni][p * 2 + 0] + bias[e * FDIM + n];
                        float v1 = acc[mi][ni][p * 2 + 1] + bias[e * FDIM + n + 1];
                        v0 = ea_gelu(v0) * wr;
                        v1 = ea_gelu(v1) * wr;
                        __nv_bfloat16 h0, l0, h1, l1;
                        ea_split(v0, h0, l0); ea_split(v1, h1, l1);
                        *(uint32_t*)(g_ghi + rowo + ni * 8 + lcol) = ea_pack2(h0, h1);
                        *(uint32_t*)(g_glo + rowo + ni * 8 + lcol) = ea_pack2(l0, l1);
                    }
                }
            }
        } else {
            const float* b2s = (const float*)(smem + SMEM_MAIN);
            #pragma unroll
            for (int mi = 0; mi < 4; mi++) {
                #pragma unroll
                for (int p = 0; p < 2; p++) {
                    const int m = bm0 + wm * 64 + mi * 16 + lrow + p * 8;
                    float4 w0 = *(const float4*)(g_router + (size_t)m * NEXP);
                    float4 w1 = *(const float4*)(g_router + (size_t)m * NEXP + 4);
                    float wr[NEXP] = {w0.x, w0.y, w0.z, w0.w, w1.x, w1.y, w1.z, w1.w};
                    float* orow = out + (size_t)m * DDIM + bn0;
                    #pragma unroll
                    for (int ni = 0; ni < 4; ni++) {
                        const int nl = wn * 32 + ni * 8 + lcol;
                        float bias0 = 0.0f, bias1 = 0.0f;
                        #pragma unroll
                        for (int ee = 0; ee < NEXP; ee++) {
                            bias0 = fmaf(wr[ee], b2s[ee * BN + nl], bias0);
                            bias1 = fmaf(wr[ee], b2s[ee * BN + nl + 1], bias1);
                        }
                        float2 res = make_float2(acc[mi][ni][p * 2 + 0] + bias0,
                                                 acc[mi][ni][p * 2 + 1] + bias1);
                        *(float2*)(orow + nl) = res;
                    }
                }
            }
        }
    }
}

// ---------------------------------------------------------------------------
extern "C" void kernel_launch(void* const* d_in, const int* in_sizes, int n_in,
                              void* d_out, int out_size)
{
    const float* x  = (const float*)d_in[0];
    const float* W1 = (const float*)d_in[1];
    const float* b1 = (const float*)d_in[2];
    const float* W2 = (const float*)d_in[3];
    const float* b2 = (const float*)d_in[4];
    const float* Wr = (const float*)d_in[5];
    const float* br = (const float*)d_in[6];
    float* out = (float*)d_out;

    cudaFuncSetAttribute(gemm_persistent_kernel<0>, cudaFuncAttributeMaxDynamicSharedMemorySize, SMEM_TOTAL);
    cudaFuncSetAttribute(gemm_persistent_kernel<1>, cudaFuncAttributeMaxDynamicSharedMemorySize, SMEM_TOTAL);

    init_sched_kernel<<<1, 32>>>();
    router_convert_kernel<<<MTOK, 256>>>(x, Wr, br);
    transpose_split_kernel<0><<<dim3(FDIM / 32, DDIM / 32, NEXP), dim3(32, 8)>>>(W1, DDIM, FDIM);
    transpose_split_kernel<1><<<dim3(DDIM / 32, KEF / 32, 1), dim3(32, 8)>>>(W2, KEF, DDIM);

    gemm_persistent_kernel<0><<<PERSIST_CTAS, 256, SMEM_TOTAL>>>(b1, nullptr);
    gemm_persistent_kernel<1><<<PERSIST_CTAS, 256, SMEM_TOTAL>>>(b2, out);
}

// round 8
// speedup vs baseline: 1.3477x; 1.2570x over previous
#include <cuda_runtime.h>
#include <cuda_bf16.h>
#include <stdint.h>
#include <math.h>

// ---------------------------------------------------------------------------
// Problem constants
// ---------------------------------------------------------------------------
#define MTOK 16384        // B*N tokens
#define DDIM 1024         // hidden dim
#define NEXP 8            // experts
#define FDIM 512          // expert dim
#define KEF  4096         // NEXP*FDIM

// GEMM tiling: block 128x128, warp tile 64x32 (8 warps: 2m x 4n), BK=32
#define BM 128
#define BN 128
#define BK 32
#define NSTAGE 3
#define OFF_AHI 0
#define OFF_ALO 8192
#define OFF_BHI 16384
#define OFF_BLO 24576
#define STAGE_BYTES 32768
#define SMEM_MAIN (NSTAGE * STAGE_BYTES)      // 96 KB
#define SMEM_TOTAL (SMEM_MAIN + 4096)         // + b2 bias tile (8x128 fp32)

// ---------------------------------------------------------------------------
// Global scratch (static __device__ — no allocation)
// ---------------------------------------------------------------------------
static __device__ __align__(256) float         g_router[MTOK * NEXP];
static __device__ __align__(256) __nv_bfloat16 g_xhi[(size_t)MTOK * DDIM];
static __device__ __align__(256) __nv_bfloat16 g_xlo[(size_t)MTOK * DDIM];
static __device__ __align__(256) __nv_bfloat16 g_w1t_hi[(size_t)NEXP * FDIM * DDIM]; // [e][f][d]
static __device__ __align__(256) __nv_bfloat16 g_w1t_lo[(size_t)NEXP * FDIM * DDIM];
static __device__ __align__(256) __nv_bfloat16 g_w2t_hi[(size_t)DDIM * KEF];         // [d][ef]
static __device__ __align__(256) __nv_bfloat16 g_w2t_lo[(size_t)DDIM * KEF];
static __device__ __align__(256) __nv_bfloat16 g_ghi[(size_t)MTOK * KEF];
static __device__ __align__(256) __nv_bfloat16 g_glo[(size_t)MTOK * KEF];

// ---------------------------------------------------------------------------
// Helpers (base ISA only)
// ---------------------------------------------------------------------------
__device__ __forceinline__ uint32_t ea_smem_u32(const void* p) {
    uint32_t a;
    asm("{ .reg .u64 t; cvta.to.shared.u64 t, %1; cvt.u32.u64 %0, t; }" : "=r"(a) : "l"(p));
    return a;
}
// Logical (row r, 16B-chunk c in 0..3) -> conflict-free physical byte offset.
__device__ __forceinline__ uint32_t ea_sw(int r, int c) {
    return ((uint32_t)(r >> 1) << 7) |
           ((uint32_t)(((((r & 1) << 2) | c) ^ ((r >> 1) & 7))) << 4);
}
__device__ __forceinline__ void ea_cp16(uint32_t s, const void* g) {
    asm volatile("cp.async.cg.shared.global.L2::256B [%0], [%1], 16;\n" :: "r"(s), "l"(g));
}
__device__ __forceinline__ void ea_cp_commit() { asm volatile("cp.async.commit_group;\n"); }
template <int N>
__device__ __forceinline__ void ea_cp_wait() { asm volatile("cp.async.wait_group %0;\n" :: "n"(N)); }

__device__ __forceinline__ void ea_ldsm4(uint32_t* r, uint32_t a) {
    asm volatile("ldmatrix.sync.aligned.m8n8.x4.shared.b16 {%0,%1,%2,%3}, [%4];\n"
                 : "=r"(r[0]), "=r"(r[1]), "=r"(r[2]), "=r"(r[3]) : "r"(a));
}
__device__ __forceinline__ void ea_mma(float* d, const uint32_t* a, uint32_t b0, uint32_t b1) {
    asm volatile(
        "mma.sync.aligned.m16n8k16.row.col.f32.bf16.bf16.f32 "
        "{%0,%1,%2,%3}, {%4,%5,%6,%7}, {%8,%9}, {%0,%1,%2,%3};\n"
        : "+f"(d[0]), "+f"(d[1]), "+f"(d[2]), "+f"(d[3])
        : "r"(a[0]), "r"(a[1]), "r"(a[2]), "r"(a[3]), "r"(b0), "r"(b1));
}
__device__ __forceinline__ uint32_t ea_pack2(__nv_bfloat16 a, __nv_bfloat16 b) {
    return (uint32_t)__bfloat16_as_ushort(a) | ((uint32_t)__bfloat16_as_ushort(b) << 16);
}
__device__ __forceinline__ void ea_split(float v, __nv_bfloat16& h, __nv_bfloat16& l) {
    h = __float2bfloat16(v);
    l = __float2bfloat16(v - __bfloat162float(h));
}
__device__ __forceinline__ float ea_gelu(float v) {
    return 0.5f * v * (1.0f + erff(v * 0.70710678118654752f));
}

// ---------------------------------------------------------------------------
// Fused router + x hi/lo split. One block per token, 256 thr = 4 floats each.
// ---------------------------------------------------------------------------
__global__ void __launch_bounds__(256) router_convert_kernel(
    const float* __restrict__ x, const float* __restrict__ Wr, const float* __restrict__ br)
{
    const int t = blockIdx.x;
    const int tid = threadIdx.x;
    const int warp = tid >> 5, lane = tid & 31;
    __shared__ float part[8][NEXP];

    const size_t base4 = (size_t)t * (DDIM / 4) + tid;   // float4 index
    float4 v = ((const float4*)x)[base4];

    __nv_bfloat16 h0, h1, h2, h3, l0, l1, l2, l3;
    ea_split(v.x, h0, l0); ea_split(v.y, h1, l1);
    ea_split(v.z, h2, l2); ea_split(v.w, h3, l3);
    ((uint2*)g_xhi)[base4] = make_uint2(ea_pack2(h0, h1), ea_pack2(h2, h3));
    ((uint2*)g_xlo)[base4] = make_uint2(ea_pack2(l0, l1), ea_pack2(l2, l3));

    const float* wr = Wr + (size_t)tid * 4 * NEXP;
    float acc[NEXP];
    #pragma unroll
    for (int e = 0; e < NEXP; e++)
        acc[e] = v.x * wr[e] + v.y * wr[NEXP + e] + v.z * wr[2 * NEXP + e] + v.w * wr[3 * NEXP + e];
    #pragma unroll
    for (int o = 16; o > 0; o >>= 1)
        #pragma unroll
        for (int e = 0; e < NEXP; e++)
            acc[e] += __shfl_xor_sync(0xffffffffu, acc[e], o);
    if (lane == 0)
        #pragma unroll
        for (int e = 0; e < NEXP; e++) part[warp][e] = acc[e];
    __syncthreads();

    if (warp == 0 && lane < NEXP) {
        float s = br[lane];
        #pragma unroll
        for (int w = 0; w < 8; w++) s += part[w][lane];
        float mx = s;
        #pragma unroll
        for (int o = 4; o > 0; o >>= 1) mx = fmaxf(mx, __shfl_xor_sync(0xffu, mx, o, 8));
        float ex = expf(s - mx);
        float tot = ex;
        #pragma unroll
        for (int o = 4; o > 0; o >>= 1) tot += __shfl_xor_sync(0xffu, tot, o, 8);
        g_router[t * NEXP + lane] = ex / tot;
    }
}

// ---------------------------------------------------------------------------
// Transposing split: src[rows][cols] fp32 -> dst[cols][rows] bf16 hi/lo
// ---------------------------------------------------------------------------
template <int WHICH>
__global__ void __launch_bounds__(256) transpose_split_kernel(
    const float* __restrict__ src, int rows, int cols)
{
    __shared__ float tile[32][33];
    const size_t zoff = (size_t)blockIdx.z * rows * cols;
    const float* s = src + zoff;
    __nv_bfloat16* dhi = (WHICH == 0 ? g_w1t_hi : g_w2t_hi) + zoff;
    __nv_bfloat16* dlo = (WHICH == 0 ? g_w1t_lo : g_w2t_lo) + zoff;

    int x = blockIdx.x * 32 + threadIdx.x;
    int y0 = blockIdx.y * 32;
    #pragma unroll
    for (int j = 0; j < 32; j += 8)
        tile[threadIdx.y + j][threadIdx.x] = s[(size_t)(y0 + threadIdx.y + j) * cols + x];
    __syncthreads();
    int xo = blockIdx.y * 32 + threadIdx.x;
    int yo = blockIdx.x * 32;
    #pragma unroll
    for (int j = 0; j < 32; j += 8) {
        float v = tile[threadIdx.x][threadIdx.y + j];
        __nv_bfloat16 h, l; ea_split(v, h, l);
        size_t o = (size_t)(yo + threadIdx.y + j) * rows + xo;
        dhi[o] = h; dlo[o] = l;
    }
}

// ---------------------------------------------------------------------------
// GEMM via mma.sync bf16x3. MODE 0 = FC1 (gelu epilogue), MODE 1 = FC2.
// 128x128 block, 3-stage cp.async pipeline, one __syncthreads per BK iter,
// 2 CTAs per SM. Pass-major MMA ordering (16 independent HMMA per pass).
// ---------------------------------------------------------------------------
template <int MODE>
__global__ void __launch_bounds__(256, 2) gemm_mma_kernel(
    const float* __restrict__ bias,   // b1 [E,F] or b2 [E,D]
    float* __restrict__ out)          // MODE 1 only
{
    extern __shared__ char smem[];
    const uint32_t sb = ea_smem_u32(smem);
    const int tid = threadIdx.x;
    const int wid = tid >> 5, lane = tid & 31;
    const int wm = wid & 1, wn = wid >> 1;    // 2 x 4 warp grid, 64x32 tiles
    const int bm0 = blockIdx.y * BM;

    int e, bn0;
    const __nv_bfloat16 *Ahi, *Alo, *Bhi, *Blo;
    int lda, ldb, nk;
    if (MODE == 0) {
        // expert-fastest CTA order: all 8 experts' weights stay L2-hot
        e = blockIdx.x >> 2;
        bn0 = (blockIdx.x & 3) * BN;
        Ahi = g_xhi; Alo = g_xlo; lda = DDIM;
        const size_t wo = (size_t)e * FDIM * DDIM;
        Bhi = g_w1t_hi + wo; Blo = g_w1t_lo + wo; ldb = DDIM;
        nk = DDIM / BK;
    } else {
        e = 0;
        bn0 = blockIdx.x * BN;
        Ahi = g_ghi; Alo = g_glo; lda = KEF;
        Bhi = g_w2t_hi; Blo = g_w2t_lo; ldb = KEF;
        nk = KEF / BK;
    }

    // FC2: stage b2 tile [8][BN] into smem once (sync'd by pipeline barriers).
    if (MODE == 1) {
        float* b2s = (float*)(smem + SMEM_MAIN);
        #pragma unroll
        for (int it = 0; it < 4; it++) {
            int idx = tid + it * 256;               // 1024 entries
            b2s[idx] = bias[(idx >> 7) * DDIM + bn0 + (idx & 127)];
        }
    }

    float acc[4][4][4];
    #pragma unroll
    for (int a = 0; a < 4; a++)
        #pragma unroll
        for (int b = 0; b < 4; b++)
            #pragma unroll
            for (int c = 0; c < 4; c++) acc[a][b][c] = 0.0f;

    auto load_stage = [&](int stg, int kk) {
        const uint32_t base = sb + stg * STAGE_BYTES;
        #pragma unroll
        for (int it = 0; it < 2; it++) {
            int idx = tid + it * 256;
            int r = idx >> 2, c = idx & 3;
            uint32_t so = ea_sw(r, c);
            size_t ga = (size_t)(bm0 + r) * lda + kk + c * 8;
            size_t gb = (size_t)(bn0 + r) * ldb + kk + c * 8;
            ea_cp16(base + OFF_AHI + so, Ahi + ga);
            ea_cp16(base + OFF_ALO + so, Alo + ga);
            ea_cp16(base + OFF_BHI + so, Bhi + gb);
            ea_cp16(base + OFF_BLO + so, Blo + gb);
        }
    };

    auto compute_stage = [&](int stg) {
        const uint32_t base = sb + stg * STAGE_BYTES;
        #pragma unroll
        for (int s = 0; s < 2; s++) {             // two k16 steps per BK
            uint32_t ah[4][4], al[4][4], bh[2][4], bl[2][4];
            const int arow = wm * 64 + (lane & 7) + ((lane >> 3) & 1) * 8;
            const int acol = s * 2 + ((lane >> 4) & 1);
            #pragma unroll
            for (int mi = 0; mi < 4; mi++) {
                uint32_t off = ea_sw(arow + mi * 16, acol);
                ea_ldsm4(ah[mi], base + OFF_AHI + off);
                ea_ldsm4(al[mi], base + OFF_ALO + off);
            }
            const int brow = wn * 32 + (lane & 7) + ((lane >> 4) & 1) * 8;
            const int bcol = s * 2 + ((lane >> 3) & 1);
            #pragma unroll
            for (int bi = 0; bi < 2; bi++) {
                uint32_t off = ea_sw(brow + bi * 16, bcol);
                ea_ldsm4(bh[bi], base + OFF_BHI + off);
                ea_ldsm4(bl[bi], base + OFF_BLO + off);
            }
            // pass-major: 16 independent HMMA per pass -> no RAW chains
            #pragma unroll
            for (int mi = 0; mi < 4; mi++)
                #pragma unroll
                for (int ni = 0; ni < 4; ni++)
                    ea_mma(acc[mi][ni], ah[mi], bh[ni >> 1][(ni & 1) * 2], bh[ni >> 1][(ni & 1) * 2 + 1]);
            #pragma unroll
            for (int mi = 0; mi < 4; mi++)
                #pragma unroll
                for (int ni = 0; ni < 4; ni++)
                    ea_mma(acc[mi][ni], ah[mi], bl[ni >> 1][(ni & 1) * 2], bl[ni >> 1][(ni & 1) * 2 + 1]);
            #pragma unroll
            for (int mi = 0; mi < 4; mi++)
                #pragma unroll
                for (int ni = 0; ni < 4; ni++)
                    ea_mma(acc[mi][ni], al[mi], bh[ni >> 1][(ni & 1) * 2], bh[ni >> 1][(ni & 1) * 2 + 1]);
        }
    };

    // 3-stage pipeline, one __syncthreads per iteration.
    load_stage(0, 0);      ea_cp_commit();
    load_stage(1, BK);     ea_cp_commit();

    #pragma unroll 1
    for (int ck = 0; ck < nk; ck++) {
        ea_cp_wait<1>();                 // stage ck resident
        __syncthreads();
        if (ck + NSTAGE - 1 < nk) load_stage((ck + NSTAGE - 1) % 3, (ck + NSTAGE - 1) * BK);
        ea_cp_commit();                  // possibly-empty group keeps the count
        compute_stage(ck % 3);
    }

    // ------------------------------ epilogue -------------------------------
    const int lrow = lane >> 2;          // 0..7
    const int lcol = (lane & 3) << 1;    // 0,2,4,6

    if (MODE == 0) {
        #pragma unroll
        for (int mi = 0; mi < 4; mi++) {
            #pragma unroll
            for (int p = 0; p < 2; p++) {
                const int m = bm0 + wm * 64 + mi * 16 + lrow + p * 8;
                const float wr = g_router[m * NEXP + e];
                const size_t rowo = (size_t)m * KEF + e * FDIM + bn0 + wn * 32;
                #pragma unroll
                for (int ni = 0; ni < 4; ni++) {
                    const int n = bn0 + wn * 32 + ni * 8 + lcol;
                    float v0 = acc[mi][ni][p * 2 + 0] + bias[e * FDIM + n];
                    float v1 = acc[mi][ni][p * 2 + 1] + bias[e * FDIM + n + 1];
                    v0 = ea_gelu(v0) * wr;
                    v1 = ea_gelu(v1) * wr;
                    __nv_bfloat16 h0, l0, h1, l1;
                    ea_split(v0, h0, l0); ea_split(v1, h1, l1);
                    *(uint32_t*)(g_ghi + rowo + ni * 8 + lcol) = ea_pack2(h0, h1);
                    *(uint32_t*)(g_glo + rowo + ni * 8 + lcol) = ea_pack2(l0, l1);
                }
            }
        }
    } else {
        const float* b2s = (const float*)(smem + SMEM_MAIN);
        #pragma unroll
        for (int mi = 0; mi < 4; mi++) {
            #pragma unroll
            for (int p = 0; p < 2; p++) {
                const int m = bm0 + wm * 64 + mi * 16 + lrow + p * 8;
                float4 w0 = *(const float4*)(g_router + (size_t)m * NEXP);
                float4 w1 = *(const float4*)(g_router + (size_t)m * NEXP + 4);
                float wr[NEXP] = {w0.x, w0.y, w0.z, w0.w, w1.x, w1.y, w1.z, w1.w};
                float* orow = out + (size_t)m * DDIM + bn0;
                #pragma unroll
                for (int ni = 0; ni < 4; ni++) {
                    const int nl = wn * 32 + ni * 8 + lcol;
                    float bias0 = 0.0f, bias1 = 0.0f;
                    #pragma unroll
                    for (int ee = 0; ee < NEXP; ee++) {
                        bias0 = fmaf(wr[ee], b2s[ee * BN + nl], bias0);
                        bias1 = fmaf(wr[ee], b2s[ee * BN + nl + 1], bias1);
                    }
                    float2 res = make_float2(acc[mi][ni][p * 2 + 0] + bias0,
                                             acc[mi][ni][p * 2 + 1] + bias1);
                    *(float2*)(orow + nl) = res;
                }
            }
        }
    }
}

// ---------------------------------------------------------------------------
extern "C" void kernel_launch(void* const* d_in, const int* in_sizes, int n_in,
                              void* d_out, int out_size)
{
    const float* x  = (const float*)d_in[0];
    const float* W1 = (const float*)d_in[1];
    const float* b1 = (const float*)d_in[2];
    const float* W2 = (const float*)d_in[3];
    const float* b2 = (const float*)d_in[4];
    const float* Wr = (const float*)d_in[5];
    const float* br = (const float*)d_in[6];
    float* out = (float*)d_out;

    cudaFuncSetAttribute(gemm_mma_kernel<0>, cudaFuncAttributeMaxDynamicSharedMemorySize, SMEM_TOTAL);
    cudaFuncSetAttribute(gemm_mma_kernel<1>, cudaFuncAttributeMaxDynamicSharedMemorySize, SMEM_TOTAL);

    router_convert_kernel<<<MTOK, 256>>>(x, Wr, br);
    transpose_split_kernel<0><<<dim3(FDIM / 32, DDIM / 32, NEXP), dim3(32, 8)>>>(W1, DDIM, FDIM);
    transpose_split_kernel<1><<<dim3(DDIM / 32, KEF / 32, 1), dim3(32, 8)>>>(W2, KEF, DDIM);

    dim3 g1((FDIM / BN) * NEXP, MTOK / BM);   // (32, 128), expert-fastest in x
    gemm_mma_kernel<0><<<g1, 256, SMEM_TOTAL>>>(b1, nullptr);

    dim3 g2(DDIM / BN, MTOK / BM);            // (8, 128)
    gemm_mma_kernel<1><<<g2, 256, SMEM_TOTAL>>>(b2, out);
}